// round 2
// baseline (speedup 1.0000x reference)
#include <cuda_runtime.h>
#include <math.h>

#define Bn 16
#define Sn 1024
#define En 1024
#define Wn 7
#define HW 3
#define KWE (Wn * En)        // 7168 floats per (t, v) weight row
#define WSTRIDE (Wn * KWE)   // 50176 floats per t

// Gate scratch: gates[t][b][v] padded to 8 -> 1024*16*8 floats = 512 KB
__device__ float g_gates[Sn][Bn][8];

// ---------------------------------------------------------------------------
// Kernel 1: logits + sigmoid.
// One block per timestep t; 8 warps; warp w owns batches {2w, 2w+1}.
// logits[b][v] = sum_{tap,e} x[b, t+tap-3, e] * weight[t, v, tap*E+e]
// ---------------------------------------------------------------------------
__global__ __launch_bounds__(256)
void gates_kernel(const float* __restrict__ x,
                  const float* __restrict__ weight,
                  const float* __restrict__ bias)
{
    const int t    = blockIdx.x;
    const int warp = threadIdx.x >> 5;
    const int lane = threadIdx.x & 31;
    const int b0   = warp * 2;

    const float* wt = weight + (size_t)t * WSTRIDE;

    float acc0[Wn], acc1[Wn];
    #pragma unroll
    for (int v = 0; v < Wn; v++) { acc0[v] = 0.0f; acc1[v] = 0.0f; }

    #pragma unroll 1
    for (int tap = 0; tap < Wn; tap++) {
        const int row = t + tap - HW;
        if (row < 0 || row >= Sn) continue;   // padded region contributes 0

        const float4* xr0 = (const float4*)(x + ((size_t)(b0    ) * Sn + row) * En);
        const float4* xr1 = (const float4*)(x + ((size_t)(b0 + 1) * Sn + row) * En);
        const float4* wr  = (const float4*)(wt + (size_t)tap * En);

        #pragma unroll 1
        for (int q = lane; q < En / 4; q += 32) {
            const float4 a = xr0[q];
            const float4 b = xr1[q];
            #pragma unroll
            for (int v = 0; v < Wn; v++) {
                const float4 w4 = wr[(size_t)v * (KWE / 4) + q];
                acc0[v] = fmaf(a.x, w4.x, acc0[v]);
                acc0[v] = fmaf(a.y, w4.y, acc0[v]);
                acc0[v] = fmaf(a.z, w4.z, acc0[v]);
                acc0[v] = fmaf(a.w, w4.w, acc0[v]);
                acc1[v] = fmaf(b.x, w4.x, acc1[v]);
                acc1[v] = fmaf(b.y, w4.y, acc1[v]);
                acc1[v] = fmaf(b.z, w4.z, acc1[v]);
                acc1[v] = fmaf(b.w, w4.w, acc1[v]);
            }
        }
    }

    // Warp-level tree reduction, then sigmoid.
    #pragma unroll
    for (int v = 0; v < Wn; v++) {
        float s0 = acc0[v], s1 = acc1[v];
        #pragma unroll
        for (int off = 16; off > 0; off >>= 1) {
            s0 += __shfl_xor_sync(0xffffffffu, s0, off);
            s1 += __shfl_xor_sync(0xffffffffu, s1, off);
        }
        if (lane == 0) {
            const float bb = bias[t * Wn + v];
            g_gates[t][b0    ][v] = 1.0f / (1.0f + expf(-(s0 + bb)));
            g_gates[t][b0 + 1][v] = 1.0f / (1.0f + expf(-(s1 + bb)));
        }
    }
}

// ---------------------------------------------------------------------------
// Kernel 2: out[b,t,e] = tanh( sum_tap gates[t][b][tap] * x[b, t+tap-3, e] )
// One block per (b, t); 256 threads, one float4 each (E/4 = 256).
// ---------------------------------------------------------------------------
__global__ __launch_bounds__(256)
void blend_kernel(const float* __restrict__ x,
                  float* __restrict__ out)
{
    const int t = blockIdx.x;
    const int b = blockIdx.y;
    const int q = threadIdx.x;

    float o0 = 0.f, o1 = 0.f, o2 = 0.f, o3 = 0.f;

    #pragma unroll
    for (int tap = 0; tap < Wn; tap++) {
        const int row = t + tap - HW;
        if (row >= 0 && row < Sn) {
            const float g = g_gates[t][b][tap];
            const float4 xv = ((const float4*)(x + ((size_t)b * Sn + row) * En))[q];
            o0 = fmaf(g, xv.x, o0);
            o1 = fmaf(g, xv.y, o1);
            o2 = fmaf(g, xv.z, o2);
            o3 = fmaf(g, xv.w, o3);
        }
    }

    float4 r;
    r.x = tanhf(o0);
    r.y = tanhf(o1);
    r.z = tanhf(o2);
    r.w = tanhf(o3);
    ((float4*)(out + ((size_t)b * Sn + t) * En))[q] = r;
}

extern "C" void kernel_launch(void* const* d_in, const int* in_sizes, int n_in,
                              void* d_out, int out_size)
{
    const float* x      = (const float*)d_in[0];
    const float* weight = (const float*)d_in[1];
    const float* bias   = (const float*)d_in[2];
    float* out          = (float*)d_out;

    gates_kernel<<<Sn, 256>>>(x, weight, bias);
    dim3 grid2(Sn, Bn);
    blend_kernel<<<grid2, 256>>>(x, out);
}

// round 3
// speedup vs baseline: 1.9071x; 1.9071x over previous
#include <cuda_runtime.h>
#include <math.h>

#define Bn 16
#define Sn 1024
#define En 1024
#define En4 (En / 4)         // 256 float4 per row
#define Wn 7
#define HW 3
#define KWE4 (Wn * En4)      // 1792 float4 per (t,v) weight row
#define WSTRIDE4 (Wn * KWE4) // 12544 float4 per t

__device__ __forceinline__ float fast_tanh(float v) {
    float r;
    asm("tanh.approx.f32 %0, %1;" : "=f"(r) : "f"(v));
    return r;
}

// One block per timestep t. 256 threads = 8 warps.
// Warp w: bg = w & 3 (batches 4bg..4bg+3), kh = w >> 2 (half of each tap's E range).
// Stage 1: logits[b][v] = sum_{tap,e} x[b, t+tap-3, e] * weight[t, v, tap*E+e]
//          (weight tap-slice staged through smem; x read direct, L1/L2-hot)
// Stage 2: gates = sigmoid(logits + bias)
// Stage 3: out[b,t,e] = tanh(sum_tap gates[b][tap] * x[b, t+tap-3, e])
__global__ __launch_bounds__(256, 2)
void soft_reordering_fused(const float* __restrict__ x,
                           const float* __restrict__ weight,
                           const float* __restrict__ bias,
                           float* __restrict__ out)
{
    __shared__ float4 s_w[Wn * En4];        // 28 KB: one tap-slice, [v][q4]
    __shared__ float  s_part[2][Bn][Wn];    // k-half partial logits
    __shared__ float  s_g[Bn][8];           // gates, padded

    const int t    = blockIdx.x;
    const int tid  = threadIdx.x;
    const int warp = tid >> 5;
    const int lane = tid & 31;
    const int bg   = warp & 3;      // batch group: batches 4bg..4bg+3
    const int kh   = warp >> 2;     // k-half: q4 in [kh*128, kh*128+128)

    const float4* x4 = (const float4*)x;
    const float4* wt = (const float4*)weight + (size_t)t * WSTRIDE4;

    float acc[4][Wn];
    #pragma unroll
    for (int j = 0; j < 4; j++)
        #pragma unroll
        for (int v = 0; v < Wn; v++) acc[j][v] = 0.0f;

    // Prefetch tap 0 weight slice into registers (7 float4 per thread).
    float4 pf[7];
    #pragma unroll
    for (int j = 0; j < 7; j++) {
        const int flat = tid + j * 256;            // [0, 1792)
        const int v = flat >> 8, e4 = flat & 255;
        pf[j] = wt[(size_t)v * KWE4 + e4];         // tap 0 offset = 0
    }

    #pragma unroll 1
    for (int tap = 0; tap < Wn; tap++) {
        __syncthreads();   // previous tap's smem reads done
        #pragma unroll
        for (int j = 0; j < 7; j++) {
            const int flat = tid + j * 256;
            s_w[flat] = pf[j];
        }
        if (tap < Wn - 1) {
            #pragma unroll
            for (int j = 0; j < 7; j++) {
                const int flat = tid + j * 256;
                const int v = flat >> 8, e4 = flat & 255;
                pf[j] = wt[(size_t)v * KWE4 + (tap + 1) * En4 + e4];
            }
        }
        __syncthreads();   // s_w ready

        const int row = t + tap - HW;
        if (row >= 0 && row < Sn) {
            #pragma unroll
            for (int i = 0; i < 4; i++) {
                const int q4 = kh * 128 + i * 32 + lane;
                float4 xv[4];
                #pragma unroll
                for (int j = 0; j < 4; j++)
                    xv[j] = x4[((size_t)(bg * 4 + j) * Sn + row) * En4 + q4];
                #pragma unroll
                for (int v = 0; v < Wn; v++) {
                    const float4 w4 = s_w[v * En4 + q4];
                    #pragma unroll
                    for (int j = 0; j < 4; j++) {
                        acc[j][v] = fmaf(xv[j].x, w4.x, acc[j][v]);
                        acc[j][v] = fmaf(xv[j].y, w4.y, acc[j][v]);
                        acc[j][v] = fmaf(xv[j].z, w4.z, acc[j][v]);
                        acc[j][v] = fmaf(xv[j].w, w4.w, acc[j][v]);
                    }
                }
            }
        }
    }

    // Warp reduce 28 partials, lane 0 publishes per k-half.
    #pragma unroll
    for (int j = 0; j < 4; j++) {
        #pragma unroll
        for (int v = 0; v < Wn; v++) {
            float s = acc[j][v];
            s += __shfl_xor_sync(0xffffffffu, s, 16);
            s += __shfl_xor_sync(0xffffffffu, s, 8);
            s += __shfl_xor_sync(0xffffffffu, s, 4);
            s += __shfl_xor_sync(0xffffffffu, s, 2);
            s += __shfl_xor_sync(0xffffffffu, s, 1);
            if (lane == 0) s_part[kh][bg * 4 + j][v] = s;
        }
    }
    __syncthreads();

    // Combine k-halves, add bias, sigmoid.
    if (tid < Bn * Wn) {
        const int b = tid / Wn, v = tid % Wn;
        const float l = s_part[0][b][v] + s_part[1][b][v] + bias[t * Wn + v];
        s_g[b][v] = 1.0f / (1.0f + __expf(-l));
    }
    __syncthreads();

    // Stage 3: gated blend + tanh. Thread owns one float4 column (En4 == 256).
    const int q4 = tid;
    #pragma unroll 1
    for (int b = 0; b < Bn; b++) {
        float o0 = 0.f, o1 = 0.f, o2 = 0.f, o3 = 0.f;
        #pragma unroll
        for (int tap = 0; tap < Wn; tap++) {
            const int row = t + tap - HW;
            if (row >= 0 && row < Sn) {
                const float g = s_g[b][tap];
                const float4 xv = x4[((size_t)b * Sn + row) * En4 + q4];
                o0 = fmaf(g, xv.x, o0);
                o1 = fmaf(g, xv.y, o1);
                o2 = fmaf(g, xv.z, o2);
                o3 = fmaf(g, xv.w, o3);
            }
        }
        float4 r;
        r.x = fast_tanh(o0);
        r.y = fast_tanh(o1);
        r.z = fast_tanh(o2);
        r.w = fast_tanh(o3);
        ((float4*)out)[((size_t)b * Sn + t) * En4 + q4] = r;
    }
}

extern "C" void kernel_launch(void* const* d_in, const int* in_sizes, int n_in,
                              void* d_out, int out_size)
{
    const float* x      = (const float*)d_in[0];
    const float* weight = (const float*)d_in[1];
    const float* bias   = (const float*)d_in[2];
    float* out          = (float*)d_out;

    soft_reordering_fused<<<Sn, 256>>>(x, weight, bias, out);
}